// round 13
// baseline (speedup 1.0000x reference)
#include <cuda_runtime.h>
#include <math.h>
#include <stdint.h>

// Problem constants
#define BATCH   8
#define TLEN    2048
#define CDIM    1024
#define HDIM    64
#define BT      (BATCH * TLEN)   // 16384 rows

#define QTILES   32
#define CHUNK    8
#define MAXSPLIT 4
#define BLOCKS_PER_BATCH 80      // sum over qt of (qt/CHUNK + 1)

// Scratch (__device__ globals per harness rules)
__device__ float g_Q[BT * HDIM];
__device__ float g_K[BT * HDIM];
__device__ float g_V[BT * HDIM];
__device__ float g_Op[BATCH * QTILES * MAXSPLIT * 64 * 64];
__device__ float g_pm[BATCH * QTILES * MAXSPLIT * 64];
__device__ float g_pl[BATCH * QTILES * MAXSPLIT * 64];

// ---------------------------------------------------------------------------
// cp.async helpers
// ---------------------------------------------------------------------------
__device__ __forceinline__ void cp16(uint32_t smem_dst, const void* gsrc) {
    asm volatile("cp.async.ca.shared.global [%0], [%1], 16;"
                 :: "r"(smem_dst), "l"(gsrc));
}
__device__ __forceinline__ void cp_commit() { asm volatile("cp.async.commit_group;"); }
__device__ __forceinline__ void cp_wait0() { asm volatile("cp.async.wait_group 0;"); }
__device__ __forceinline__ void cp_wait1() { asm volatile("cp.async.wait_group 1;"); }

// ---------------------------------------------------------------------------
// f32x2 packed helpers (exact fp32)
// ---------------------------------------------------------------------------
__device__ __forceinline__ unsigned long long dup2(float a) {
    unsigned long long r;
    asm("mov.b64 %0, {%1, %1};" : "=l"(r) : "f"(a));
    return r;
}
__device__ __forceinline__ void ffma2(unsigned long long& acc,
                                      unsigned long long a,
                                      unsigned long long b) {
    asm("fma.rn.f32x2 %0, %1, %2, %0;" : "+l"(acc) : "l"(a), "l"(b));
}
__device__ __forceinline__ float2 unpack2(unsigned long long v) {
    float lo, hi;
    asm("mov.b64 {%0, %1}, %2;" : "=f"(lo), "=f"(hi) : "l"(v));
    return make_float2(lo, hi);
}

// ----------------------------------------------------------------------------
// Kernel 1: fused QKV projection, f32x2, cp.async pipelined.
// 256 blocks x 64 rows x 128 threads (16 tx x 8 ty); thread tile =
// 8 rows x 4 cols x 3 mats. Raises smem reuse: 0.83 B/FMA vs 1.33 before
// (qkv was L1/crossbar-bound at 77%).
// ----------------------------------------------------------------------------
__global__ __launch_bounds__(128) void qkv_proj(
    const float* __restrict__ x,
    const float* __restrict__ Wq,
    const float* __restrict__ Wk,
    const float* __restrict__ Wv)
{
    __shared__ float xs[16][64];            // [kk][row]
    __shared__ float ws[2][3][16][64];      // double-buffered W tiles

    const int tid = threadIdx.x;
    const int tx  = tid & 15;               // 0..15 (col group)
    const int ty  = tid >> 4;               // 0..7  (row group, 8 rows each)
    const int rowBase = blockIdx.x * 64;

    const uint32_t ws_base = (uint32_t)__cvta_generic_to_shared(&ws[0][0][0][0]);
    const uint32_t ws_buf_bytes = 3 * 16 * 64 * 4;

    const float* Wmat[3] = {Wq, Wk, Wv};

    // x loader: 256 float4 slots / 128 threads = 2 each
    // slot i: r = i>>2 (0..63), k4 = (i&3)*4
    float4 xreg[2];
    #pragma unroll
    for (int j = 0; j < 2; j++) {
        const int i = tid + j * 128;
        xreg[j] = *(const float4*)&x[(size_t)(rowBase + (i >> 2)) * CDIM + 0 + (i & 3) * 4];
    }
    {
        #pragma unroll
        for (int m = 0; m < 3; m++)
            #pragma unroll
            for (int j = 0; j < 2; j++) {
                const int i = tid + j * 128;
                const int kk = i >> 4, c4 = (i & 15) * 4;
                cp16(ws_base + (uint32_t)m * (16 * 64 * 4)
                             + (uint32_t)((kk * 64 + c4) * 4),
                     &Wmat[m][(size_t)(0 + kk) * HDIM + c4]);
            }
        cp_commit();
    }

    unsigned long long acc2[3][8][2];
    #pragma unroll
    for (int m = 0; m < 3; m++)
        #pragma unroll
        for (int r = 0; r < 8; r++) {
            acc2[m][r][0] = 0ULL;
            acc2[m][r][1] = 0ULL;
        }

    int buf = 0;
    for (int k0 = 0; k0 < CDIM; k0 += 16, buf ^= 1) {
        // Stage x regs into smem (transposed)
        #pragma unroll
        for (int j = 0; j < 2; j++) {
            const int i  = tid + j * 128;
            const int r  = i >> 2;
            const int k4 = (i & 3) * 4;
            xs[k4 + 0][r] = xreg[j].x;
            xs[k4 + 1][r] = xreg[j].y;
            xs[k4 + 2][r] = xreg[j].z;
            xs[k4 + 3][r] = xreg[j].w;
        }

        const bool has_next = (k0 + 16) < CDIM;
        if (has_next) {
            const uint32_t dbase = ws_base + (uint32_t)(buf ^ 1) * ws_buf_bytes;
            #pragma unroll
            for (int m = 0; m < 3; m++)
                #pragma unroll
                for (int j = 0; j < 2; j++) {
                    const int i = tid + j * 128;
                    const int kk = i >> 4, c4 = (i & 15) * 4;
                    cp16(dbase + (uint32_t)m * (16 * 64 * 4)
                               + (uint32_t)((kk * 64 + c4) * 4),
                         &Wmat[m][(size_t)(k0 + 16 + kk) * HDIM + c4]);
                }
            cp_commit();
            cp_wait1();
        } else {
            cp_wait0();
        }
        __syncthreads();

        if (has_next) {
            #pragma unroll
            for (int j = 0; j < 2; j++) {
                const int i = tid + j * 128;
                xreg[j] = *(const float4*)&x[(size_t)(rowBase + (i >> 2)) * CDIM
                                             + k0 + 16 + (i & 3) * 4];
            }
        }

        #pragma unroll
        for (int kk = 0; kk < 16; kk++) {
            const float4 a4lo = *(const float4*)&xs[kk][ty * 8];
            const float4 a4hi = *(const float4*)&xs[kk][ty * 8 + 4];
            unsigned long long ad[8];
            ad[0] = dup2(a4lo.x); ad[1] = dup2(a4lo.y);
            ad[2] = dup2(a4lo.z); ad[3] = dup2(a4lo.w);
            ad[4] = dup2(a4hi.x); ad[5] = dup2(a4hi.y);
            ad[6] = dup2(a4hi.z); ad[7] = dup2(a4hi.w);
            #pragma unroll
            for (int m = 0; m < 3; m++) {
                const ulonglong2 b2 = *(const ulonglong2*)&ws[buf][m][kk][tx * 4];
                #pragma unroll
                for (int r = 0; r < 8; r++) {
                    ffma2(acc2[m][r][0], ad[r], b2.x);
                    ffma2(acc2[m][r][1], ad[r], b2.y);
                }
            }
        }
        __syncthreads();
    }

    #pragma unroll
    for (int r = 0; r < 8; r++) {
        const int row = rowBase + ty * 8 + r;
        const int col = tx * 4;
        float2 qlo = unpack2(acc2[0][r][0]), qhi = unpack2(acc2[0][r][1]);
        float2 klo = unpack2(acc2[1][r][0]), khi = unpack2(acc2[1][r][1]);
        float2 vlo = unpack2(acc2[2][r][0]), vhi = unpack2(acc2[2][r][1]);
        *(float4*)&g_Q[(size_t)row * HDIM + col] = make_float4(qlo.x, qlo.y, qhi.x, qhi.y);
        *(float4*)&g_K[(size_t)row * HDIM + col] = make_float4(klo.x, klo.y, khi.x, khi.y);
        *(float4*)&g_V[(size_t)row * HDIM + col] = make_float4(vlo.x, vlo.y, vhi.x, vhi.y);
    }
}

// ----------------------------------------------------------------------------
// Kernel 2: causal flash attention, split-K, scalar fp32, LPT ordering
// (unchanged from R9 best, 383.7us).
// ----------------------------------------------------------------------------
#define PAD 68
#define ATTN_SMEM (6 * 64 * PAD * sizeof(float))   // 104448 bytes

__global__ __launch_bounds__(256) void attn_kernel()
{
    extern __shared__ float smem[];
    float* qs  = smem;
    float* ksb[2] = { qs + 1 * 64 * PAD, qs + 2 * 64 * PAD };
    float* vsb[2] = { qs + 3 * 64 * PAD, qs + 4 * 64 * PAD };
    float* ps  = qs + 5 * 64 * PAD;

    const uint32_t sbase = (uint32_t)__cvta_generic_to_shared(smem);

    // LPT: reverse linear id so qt=31 (8-iter) blocks start first
    int lin = (BLOCKS_PER_BATCH - 1) - blockIdx.x;
    int qt = 0;
    while (true) {
        const int S = qt / CHUNK + 1;
        if (lin < S) break;
        lin -= S;
        qt++;
    }
    const int sp  = lin;
    const int kt0 = sp * CHUNK;
    const int kt1 = min(kt0 + CHUNK, qt + 1);

    const int b   = blockIdx.y;
    const int tid = threadIdx.x;
    const int tx  = tid & 15;
    const int ty  = tid >> 4;
    const float scale = 0.125f;

    const float* Kbase = g_K + (size_t)b * TLEN * HDIM;
    const float* Vbase = g_V + (size_t)b * TLEN * HDIM;

    {
        const float* Kb = Kbase + (size_t)kt0 * 64 * HDIM;
        const float* Vb = Vbase + (size_t)kt0 * 64 * HDIM;
        const uint32_t ks_off = sbase + (uint32_t)(1 * 64 * PAD) * 4;
        const uint32_t vs_off = sbase + (uint32_t)(3 * 64 * PAD) * 4;
        #pragma unroll
        for (int i = tid; i < 1024; i += 256) {
            const int r  = i >> 4;
            const int c4 = (i & 15) * 4;
            const uint32_t d = (uint32_t)((r * PAD + c4) * 4);
            cp16(ks_off + d, &Kb[r * HDIM + c4]);
            cp16(vs_off + d, &Vb[r * HDIM + c4]);
        }
        cp_commit();
    }

    {
        const float* Qb = g_Q + (size_t)(b * TLEN + qt * 64) * HDIM;
        #pragma unroll
        for (int i = tid; i < 1024; i += 256) {
            const int r  = i >> 4;
            const int c4 = (i & 15) * 4;
            float4 v = *(const float4*)&Qb[r * HDIM + c4];
            v.x *= scale; v.y *= scale; v.z *= scale; v.w *= scale;
            *(float4*)&qs[r * PAD + c4] = v;
        }
    }

    float m_i[4], l_i[4], acc[4][4];
    #pragma unroll
    for (int r = 0; r < 4; r++) {
        m_i[r] = -1e30f;
        l_i[r] = 0.0f;
        #pragma unroll
        for (int c = 0; c < 4; c++) acc[r][c] = 0.0f;
    }

    int buf = 0;
    for (int kt = kt0; kt < kt1; kt++, buf ^= 1) {
        const bool has_next = (kt + 1) < kt1;
        if (has_next) {
            const float* Kb = Kbase + (size_t)(kt + 1) * 64 * HDIM;
            const float* Vb = Vbase + (size_t)(kt + 1) * 64 * HDIM;
            const uint32_t ks_off = sbase + (uint32_t)((1 + (buf ^ 1)) * 64 * PAD) * 4;
            const uint32_t vs_off = sbase + (uint32_t)((3 + (buf ^ 1)) * 64 * PAD) * 4;
            #pragma unroll
            for (int i = tid; i < 1024; i += 256) {
                const int r  = i >> 4;
                const int c4 = (i & 15) * 4;
                const uint32_t d = (uint32_t)((r * PAD + c4) * 4);
                cp16(ks_off + d, &Kb[r * HDIM + c4]);
                cp16(vs_off + d, &Vb[r * HDIM + c4]);
            }
            cp_commit();
            cp_wait1();
        } else {
            cp_wait0();
        }
        __syncthreads();

        const float* ks = ksb[buf];
        const float* vs = vsb[buf];

        float s[4][4] = {};
        #pragma unroll
        for (int d = 0; d < HDIM; d += 4) {
            float4 q4[4], k4[4];
            #pragma unroll
            for (int r = 0; r < 4; r++) q4[r] = *(const float4*)&qs[(ty * 4 + r) * PAD + d];
            #pragma unroll
            for (int c = 0; c < 4; c++) k4[c] = *(const float4*)&ks[(tx * 4 + c) * PAD + d];
            #pragma unroll
            for (int r = 0; r < 4; r++)
                #pragma unroll
                for (int c = 0; c < 4; c++) {
                    s[r][c] += q4[r].x * k4[c].x;
                    s[r][c] += q4[r].y * k4[c].y;
                    s[r][c] += q4[r].z * k4[c].z;
                    s[r][c] += q4[r].w * k4[c].w;
                }
        }

        if (kt == qt) {
            #pragma unroll
            for (int r = 0; r < 4; r++)
                #pragma unroll
                for (int c = 0; c < 4; c++)
                    if (tx * 4 + c > ty * 4 + r) s[r][c] = -1e30f;
        }

        #pragma unroll
        for (int r = 0; r < 4; r++) {
            float mx = fmaxf(fmaxf(s[r][0], s[r][1]), fmaxf(s[r][2], s[r][3]));
            #pragma unroll
            for (int o = 8; o >= 1; o >>= 1)
                mx = fmaxf(mx, __shfl_xor_sync(0xffffffffu, mx, o));
            const float mnew = fmaxf(m_i[r], mx);

            float sum = 0.0f;
            #pragma unroll
            for (int c = 0; c < 4; c++) {
                s[r][c] = __expf(s[r][c] - mnew);
                sum += s[r][c];
            }
            #pragma unroll
            for (int o = 8; o >= 1; o >>= 1)
                sum += __shfl_xor_sync(0xffffffffu, sum, o);

            const float corr = __expf(m_i[r] - mnew);
            l_i[r] = l_i[r] * corr + sum;
            #pragma unroll
            for (int c = 0; c < 4; c++) acc[r][c] *= corr;
            m_i[r] = mnew;
        }

        #pragma unroll
        for (int r = 0; r < 4; r++)
            *(float4*)&ps[(ty * 4 + r) * PAD + tx * 4] =
                make_float4(s[r][0], s[r][1], s[r][2], s[r][3]);
        __syncthreads();

        #pragma unroll
        for (int j = 0; j < 64; j += 4) {
            float4 p4[4], vv[4];
            #pragma unroll
            for (int r = 0; r < 4; r++) p4[r] = *(const float4*)&ps[(ty * 4 + r) * PAD + j];
            #pragma unroll
            for (int jj = 0; jj < 4; jj++) vv[jj] = *(const float4*)&vs[(j + jj) * PAD + tx * 4];
            #pragma unroll
            for (int r = 0; r < 4; r++) {
                acc[r][0] += p4[r].x * vv[0].x + p4[r].y * vv[1].x + p4[r].z * vv[2].x + p4[r].w * vv[3].x;
                acc[r][1] += p4[r].x * vv[0].y + p4[r].y * vv[1].y + p4[r].z * vv[2].y + p4[r].w * vv[3].y;
                acc[r][2] += p4[r].x * vv[0].z + p4[r].y * vv[1].z + p4[r].z * vv[2].z + p4[r].w * vv[3].z;
                acc[r][3] += p4[r].x * vv[0].w + p4[r].y * vv[1].w + p4[r].z * vv[2].w + p4[r].w * vv[3].w;
            }
        }
        __syncthreads();
    }

    const size_t pbase = (size_t)((b * QTILES + qt) * MAXSPLIT + sp);
    float* Ob = g_Op + pbase * 4096;
    #pragma unroll
    for (int r = 0; r < 4; r++) {
        *(float4*)&Ob[(ty * 4 + r) * 64 + tx * 4] =
            make_float4(acc[r][0], acc[r][1], acc[r][2], acc[r][3]);
    }
    if (tx == 0) {
        #pragma unroll
        for (int r = 0; r < 4; r++) {
            g_pm[pbase * 64 + ty * 4 + r] = m_i[r];
            g_pl[pbase * 64 + ty * 4 + r] = l_i[r];
        }
    }
}

// ----------------------------------------------------------------------------
// Kernel 3: combine split-K partials (unchanged).
// ----------------------------------------------------------------------------
__global__ __launch_bounds__(256) void attn_combine(float* __restrict__ out)
{
    const int qt  = blockIdx.x;
    const int b   = blockIdx.y;
    const int S   = qt / CHUNK + 1;
    const int tid = threadIdx.x;
    const int tx  = tid & 15;
    const int ty  = tid >> 4;

    const size_t base = (size_t)(b * QTILES + qt) * MAXSPLIT;
    float* Ob = out + (size_t)(b * TLEN + qt * 64) * HDIM;

    #pragma unroll
    for (int r = 0; r < 4; r++) {
        const int row = ty * 4 + r;

        float ms[MAXSPLIT], ls[MAXSPLIT], sc[MAXSPLIT];
        float mstar = -1e30f;
        for (int s = 0; s < S; s++) {
            ms[s] = g_pm[(base + s) * 64 + row];
            ls[s] = g_pl[(base + s) * 64 + row];
            mstar = fmaxf(mstar, ms[s]);
        }
        float lstar = 0.0f;
        for (int s = 0; s < S; s++) {
            sc[s] = __expf(ms[s] - mstar);
            lstar += ls[s] * sc[s];
        }
        const float inv = 1.0f / lstar;

        float4 o = make_float4(0.f, 0.f, 0.f, 0.f);
        for (int s = 0; s < S; s++) {
            const float4 p = *(const float4*)&g_Op[(base + s) * 4096 + row * 64 + tx * 4];
            o.x += p.x * sc[s];
            o.y += p.y * sc[s];
            o.z += p.z * sc[s];
            o.w += p.w * sc[s];
        }
        o.x *= inv; o.y *= inv; o.z *= inv; o.w *= inv;
        *(float4*)&Ob[row * HDIM + tx * 4] = o;
    }
}

// ----------------------------------------------------------------------------
// Harness entry
// ----------------------------------------------------------------------------
extern "C" void kernel_launch(void* const* d_in, const int* in_sizes, int n_in,
                              void* d_out, int out_size)
{
    const float* x  = (const float*)d_in[0];
    const float* Wq = (const float*)d_in[1];
    const float* Wk = (const float*)d_in[2];
    const float* Wv = (const float*)d_in[3];
    float* out = (float*)d_out;

    (void)in_sizes; (void)n_in; (void)out_size;

    qkv_proj<<<BT / 64, 128>>>(x, Wq, Wk, Wv);

    cudaFuncSetAttribute(attn_kernel, cudaFuncAttributeMaxDynamicSharedMemorySize,
                         (int)ATTN_SMEM);
    attn_kernel<<<dim3(BLOCKS_PER_BATCH, BATCH), 256, ATTN_SMEM>>>();

    attn_combine<<<dim3(QTILES, BATCH), 256>>>(out);
}

// round 14
// speedup vs baseline: 2.0383x; 2.0383x over previous
#include <cuda_runtime.h>
#include <math.h>
#include <stdint.h>

// Problem constants
#define BATCH   8
#define TLEN    2048
#define CDIM    1024
#define HDIM    64
#define BT      (BATCH * TLEN)   // 16384 rows

#define QTILES   32
#define CHUNK    8
#define MAXSPLIT 4
#define BLOCKS_PER_BATCH 80      // sum over qt of (qt/CHUNK + 1)

// qkv grid: 56-row slabs, 293 blocks -> single wave on 148 SMs x 2 resident
#define QKV_ROWS   56
#define QKV_BLOCKS 293           // ceil(16384 / 56)
#define QKV_THREADS 224          // 14 ty-groups x 16 tx

// Scratch (__device__ globals per harness rules)
__device__ float g_Q[BT * HDIM];
__device__ float g_K[BT * HDIM];
__device__ float g_V[BT * HDIM];
__device__ float g_Op[BATCH * QTILES * MAXSPLIT * 64 * 64];
__device__ float g_pm[BATCH * QTILES * MAXSPLIT * 64];
__device__ float g_pl[BATCH * QTILES * MAXSPLIT * 64];

// ---------------------------------------------------------------------------
// cp.async helpers
// ---------------------------------------------------------------------------
__device__ __forceinline__ void cp16(uint32_t smem_dst, const void* gsrc) {
    asm volatile("cp.async.ca.shared.global [%0], [%1], 16;"
                 :: "r"(smem_dst), "l"(gsrc));
}
__device__ __forceinline__ void cp_commit() { asm volatile("cp.async.commit_group;"); }
__device__ __forceinline__ void cp_wait0() { asm volatile("cp.async.wait_group 0;"); }
__device__ __forceinline__ void cp_wait1() { asm volatile("cp.async.wait_group 1;"); }

// ---------------------------------------------------------------------------
// f32x2 packed helpers (exact fp32)
// ---------------------------------------------------------------------------
__device__ __forceinline__ unsigned long long dup2(float a) {
    unsigned long long r;
    asm("mov.b64 %0, {%1, %1};" : "=l"(r) : "f"(a));
    return r;
}
__device__ __forceinline__ void ffma2(unsigned long long& acc,
                                      unsigned long long a,
                                      unsigned long long b) {
    asm("fma.rn.f32x2 %0, %1, %2, %0;" : "+l"(acc) : "l"(a), "l"(b));
}
__device__ __forceinline__ float2 unpack2(unsigned long long v) {
    float lo, hi;
    asm("mov.b64 {%0, %1}, %2;" : "=f"(lo), "=f"(hi) : "l"(v));
    return make_float2(lo, hi);
}

// ----------------------------------------------------------------------------
// Kernel 1: fused QKV projection (exact R9 config: measured 149us).
// 293 blocks x 56 rows x 224 threads, 4x4x3 thread tile, f32x2, cp.async.
// ----------------------------------------------------------------------------
__global__ __launch_bounds__(QKV_THREADS) void qkv_proj(
    const float* __restrict__ x,
    const float* __restrict__ Wq,
    const float* __restrict__ Wk,
    const float* __restrict__ Wv)
{
    __shared__ float xs[16][QKV_ROWS];      // [kk][row]
    __shared__ float ws[2][3][16][64];      // double-buffered W tiles

    const int tid = threadIdx.x;
    const int tx  = tid & 15;               // 0..15 (col group)
    const int ty  = tid >> 4;               // 0..13 (row group)
    const int rowBase = min(blockIdx.x * QKV_ROWS, BT - QKV_ROWS);

    const uint32_t ws_base = (uint32_t)__cvta_generic_to_shared(&ws[0][0][0][0]);
    const uint32_t ws_buf_bytes = 3 * 16 * 64 * 4;

    const int xr  = tid >> 2;               // 0..55
    const int xk4 = (tid & 3) * 4;          // 0,4,8,12

    const float* Wmat[3] = {Wq, Wk, Wv};

    float4 xreg = *(const float4*)&x[(size_t)(rowBase + xr) * CDIM + 0 + xk4];
    {
        #pragma unroll
        for (int m = 0; m < 3; m++)
            for (int i = tid; i < 256; i += QKV_THREADS) {
                const int kk = i >> 4, c4 = (i & 15) * 4;
                cp16(ws_base + (uint32_t)m * (16 * 64 * 4)
                             + (uint32_t)((kk * 64 + c4) * 4),
                     &Wmat[m][(size_t)(0 + kk) * HDIM + c4]);
            }
        cp_commit();
    }

    unsigned long long acc2[3][4][2];
    #pragma unroll
    for (int m = 0; m < 3; m++)
        #pragma unroll
        for (int r = 0; r < 4; r++) {
            acc2[m][r][0] = 0ULL;
            acc2[m][r][1] = 0ULL;
        }

    int buf = 0;
    for (int k0 = 0; k0 < CDIM; k0 += 16, buf ^= 1) {
        xs[xk4 + 0][xr] = xreg.x;
        xs[xk4 + 1][xr] = xreg.y;
        xs[xk4 + 2][xr] = xreg.z;
        xs[xk4 + 3][xr] = xreg.w;

        const bool has_next = (k0 + 16) < CDIM;
        if (has_next) {
            const uint32_t dbase = ws_base + (uint32_t)(buf ^ 1) * ws_buf_bytes;
            #pragma unroll
            for (int m = 0; m < 3; m++)
                for (int i = tid; i < 256; i += QKV_THREADS) {
                    const int kk = i >> 4, c4 = (i & 15) * 4;
                    cp16(dbase + (uint32_t)m * (16 * 64 * 4)
                               + (uint32_t)((kk * 64 + c4) * 4),
                         &Wmat[m][(size_t)(k0 + 16 + kk) * HDIM + c4]);
                }
            cp_commit();
            cp_wait1();
        } else {
            cp_wait0();
        }
        __syncthreads();

        if (has_next)
            xreg = *(const float4*)&x[(size_t)(rowBase + xr) * CDIM + k0 + 16 + xk4];

        #pragma unroll
        for (int kk = 0; kk < 16; kk++) {
            const float4 a4 = *(const float4*)&xs[kk][ty * 4];
            unsigned long long ad[4];
            ad[0] = dup2(a4.x); ad[1] = dup2(a4.y);
            ad[2] = dup2(a4.z); ad[3] = dup2(a4.w);
            #pragma unroll
            for (int m = 0; m < 3; m++) {
                const ulonglong2 b2 = *(const ulonglong2*)&ws[buf][m][kk][tx * 4];
                #pragma unroll
                for (int r = 0; r < 4; r++) {
                    ffma2(acc2[m][r][0], ad[r], b2.x);
                    ffma2(acc2[m][r][1], ad[r], b2.y);
                }
            }
        }
        __syncthreads();
    }

    #pragma unroll
    for (int r = 0; r < 4; r++) {
        const int row = rowBase + ty * 4 + r;
        const int col = tx * 4;
        float2 qlo = unpack2(acc2[0][r][0]), qhi = unpack2(acc2[0][r][1]);
        float2 klo = unpack2(acc2[1][r][0]), khi = unpack2(acc2[1][r][1]);
        float2 vlo = unpack2(acc2[2][r][0]), vhi = unpack2(acc2[2][r][1]);
        *(float4*)&g_Q[(size_t)row * HDIM + col] = make_float4(qlo.x, qlo.y, qhi.x, qhi.y);
        *(float4*)&g_K[(size_t)row * HDIM + col] = make_float4(klo.x, klo.y, khi.x, khi.y);
        *(float4*)&g_V[(size_t)row * HDIM + col] = make_float4(vlo.x, vlo.y, vhi.x, vhi.y);
    }
}

// ----------------------------------------------------------------------------
// Kernel 2: causal flash attention, split-K, LPT ordering.
// BANK-CONFLICT FIX: score columns owned STRIDED (tx + 16*c) instead of
// blocked (tx*4+c). K row stride 272B = 16 mod 128B meant blocked ownership
// put all 16 lanes' 16B loads on 2 bank groups (8-way conflict, 8 phases);
// strided ownership spreads them over all 32 banks (2 phases, optimal).
// ----------------------------------------------------------------------------
#define PAD 68
#define ATTN_SMEM (6 * 64 * PAD * sizeof(float))   // 104448 bytes

__global__ __launch_bounds__(256) void attn_kernel()
{
    extern __shared__ float smem[];
    float* qs  = smem;
    float* ksb[2] = { qs + 1 * 64 * PAD, qs + 2 * 64 * PAD };
    float* vsb[2] = { qs + 3 * 64 * PAD, qs + 4 * 64 * PAD };
    float* ps  = qs + 5 * 64 * PAD;

    const uint32_t sbase = (uint32_t)__cvta_generic_to_shared(smem);

    // LPT: reverse linear id so qt=31 (8-iter) blocks start first
    int lin = (BLOCKS_PER_BATCH - 1) - blockIdx.x;
    int qt = 0;
    while (true) {
        const int S = qt / CHUNK + 1;
        if (lin < S) break;
        lin -= S;
        qt++;
    }
    const int sp  = lin;
    const int kt0 = sp * CHUNK;
    const int kt1 = min(kt0 + CHUNK, qt + 1);

    const int b   = blockIdx.y;
    const int tid = threadIdx.x;
    const int tx  = tid & 15;
    const int ty  = tid >> 4;
    const float scale = 0.125f;

    const float* Kbase = g_K + (size_t)b * TLEN * HDIM;
    const float* Vbase = g_V + (size_t)b * TLEN * HDIM;

    {
        const float* Kb = Kbase + (size_t)kt0 * 64 * HDIM;
        const float* Vb = Vbase + (size_t)kt0 * 64 * HDIM;
        const uint32_t ks_off = sbase + (uint32_t)(1 * 64 * PAD) * 4;
        const uint32_t vs_off = sbase + (uint32_t)(3 * 64 * PAD) * 4;
        #pragma unroll
        for (int i = tid; i < 1024; i += 256) {
            const int r  = i >> 4;
            const int c4 = (i & 15) * 4;
            const uint32_t d = (uint32_t)((r * PAD + c4) * 4);
            cp16(ks_off + d, &Kb[r * HDIM + c4]);
            cp16(vs_off + d, &Vb[r * HDIM + c4]);
        }
        cp_commit();
    }

    {
        const float* Qb = g_Q + (size_t)(b * TLEN + qt * 64) * HDIM;
        #pragma unroll
        for (int i = tid; i < 1024; i += 256) {
            const int r  = i >> 4;
            const int c4 = (i & 15) * 4;
            float4 v = *(const float4*)&Qb[r * HDIM + c4];
            v.x *= scale; v.y *= scale; v.z *= scale; v.w *= scale;
            *(float4*)&qs[r * PAD + c4] = v;
        }
    }

    float m_i[4], l_i[4], acc[4][4];
    #pragma unroll
    for (int r = 0; r < 4; r++) {
        m_i[r] = -1e30f;
        l_i[r] = 0.0f;
        #pragma unroll
        for (int c = 0; c < 4; c++) acc[r][c] = 0.0f;
    }

    int buf = 0;
    for (int kt = kt0; kt < kt1; kt++, buf ^= 1) {
        const bool has_next = (kt + 1) < kt1;
        if (has_next) {
            const float* Kb = Kbase + (size_t)(kt + 1) * 64 * HDIM;
            const float* Vb = Vbase + (size_t)(kt + 1) * 64 * HDIM;
            const uint32_t ks_off = sbase + (uint32_t)((1 + (buf ^ 1)) * 64 * PAD) * 4;
            const uint32_t vs_off = sbase + (uint32_t)((3 + (buf ^ 1)) * 64 * PAD) * 4;
            #pragma unroll
            for (int i = tid; i < 1024; i += 256) {
                const int r  = i >> 4;
                const int c4 = (i & 15) * 4;
                const uint32_t d = (uint32_t)((r * PAD + c4) * 4);
                cp16(ks_off + d, &Kb[r * HDIM + c4]);
                cp16(vs_off + d, &Vb[r * HDIM + c4]);
            }
            cp_commit();
            cp_wait1();
        } else {
            cp_wait0();
        }
        __syncthreads();

        const float* ks = ksb[buf];
        const float* vs = vsb[buf];

        // Scores: thread owns STRIDED columns tx + 16*c (bank-conflict-free)
        float s[4][4] = {};
        #pragma unroll
        for (int d = 0; d < HDIM; d += 4) {
            float4 q4[4], k4[4];
            #pragma unroll
            for (int r = 0; r < 4; r++) q4[r] = *(const float4*)&qs[(ty * 4 + r) * PAD + d];
            #pragma unroll
            for (int c = 0; c < 4; c++) k4[c] = *(const float4*)&ks[(tx + 16 * c) * PAD + d];
            #pragma unroll
            for (int r = 0; r < 4; r++)
                #pragma unroll
                for (int c = 0; c < 4; c++) {
                    s[r][c] += q4[r].x * k4[c].x;
                    s[r][c] += q4[r].y * k4[c].y;
                    s[r][c] += q4[r].z * k4[c].z;
                    s[r][c] += q4[r].w * k4[c].w;
                }
        }

        // Causal mask on the diagonal tile (strided column index)
        if (kt == qt) {
            #pragma unroll
            for (int r = 0; r < 4; r++)
                #pragma unroll
                for (int c = 0; c < 4; c++)
                    if (tx + 16 * c > ty * 4 + r) s[r][c] = -1e30f;
        }

        // Online softmax update (row reductions across the 16 tx lanes)
        #pragma unroll
        for (int r = 0; r < 4; r++) {
            float mx = fmaxf(fmaxf(s[r][0], s[r][1]), fmaxf(s[r][2], s[r][3]));
            #pragma unroll
            for (int o = 8; o >= 1; o >>= 1)
                mx = fmaxf(mx, __shfl_xor_sync(0xffffffffu, mx, o));
            const float mnew = fmaxf(m_i[r], mx);

            float sum = 0.0f;
            #pragma unroll
            for (int c = 0; c < 4; c++) {
                s[r][c] = __expf(s[r][c] - mnew);
                sum += s[r][c];
            }
            #pragma unroll
            for (int o = 8; o >= 1; o >>= 1)
                sum += __shfl_xor_sync(0xffffffffu, sum, o);

            const float corr = __expf(m_i[r] - mnew);
            l_i[r] = l_i[r] * corr + sum;
            #pragma unroll
            for (int c = 0; c < 4; c++) acc[r][c] *= corr;
            m_i[r] = mnew;
        }

        // Stage P to shared at strided columns (scalar stores; 32 lanes of a
        // warp hit 32 distinct banks -> conflict-free)
        #pragma unroll
        for (int r = 0; r < 4; r++)
            #pragma unroll
            for (int c = 0; c < 4; c++)
                ps[(ty * 4 + r) * PAD + tx + 16 * c] = s[r][c];
        __syncthreads();

        // O += P . V (unchanged: ps reads broadcast, vs reads contiguous)
        #pragma unroll
        for (int j = 0; j < 64; j += 4) {
            float4 p4[4], vv[4];
            #pragma unroll
            for (int r = 0; r < 4; r++) p4[r] = *(const float4*)&ps[(ty * 4 + r) * PAD + j];
            #pragma unroll
            for (int jj = 0; jj < 4; jj++) vv[jj] = *(const float4*)&vs[(j + jj) * PAD + tx * 4];
            #pragma unroll
            for (int r = 0; r < 4; r++) {
                acc[r][0] += p4[r].x * vv[0].x + p4[r].y * vv[1].x + p4[r].z * vv[2].x + p4[r].w * vv[3].x;
                acc[r][1] += p4[r].x * vv[0].y + p4[r].y * vv[1].y + p4[r].z * vv[2].y + p4[r].w * vv[3].y;
                acc[r][2] += p4[r].x * vv[0].z + p4[r].y * vv[1].z + p4[r].z * vv[2].z + p4[r].w * vv[3].z;
                acc[r][3] += p4[r].x * vv[0].w + p4[r].y * vv[1].w + p4[r].z * vv[2].w + p4[r].w * vv[3].w;
            }
        }
        __syncthreads();
    }

    // Write unnormalized partials + (m, l)
    const size_t pbase = (size_t)((b * QTILES + qt) * MAXSPLIT + sp);
    float* Ob = g_Op + pbase * 4096;
    #pragma unroll
    for (int r = 0; r < 4; r++) {
        *(float4*)&Ob[(ty * 4 + r) * 64 + tx * 4] =
            make_float4(acc[r][0], acc[r][1], acc[r][2], acc[r][3]);
    }
    if (tx == 0) {
        #pragma unroll
        for (int r = 0; r < 4; r++) {
            g_pm[pbase * 64 + ty * 4 + r] = m_i[r];
            g_pl[pbase * 64 + ty * 4 + r] = l_i[r];
        }
    }
}

// ----------------------------------------------------------------------------
// Kernel 3: combine split-K partials (unchanged).
// ----------------------------------------------------------------------------
__global__ __launch_bounds__(256) void attn_combine(float* __restrict__ out)
{
    const int qt  = blockIdx.x;
    const int b   = blockIdx.y;
    const int S   = qt / CHUNK + 1;
    const int tid = threadIdx.x;
    const int tx  = tid & 15;
    const int ty  = tid >> 4;

    const size_t base = (size_t)(b * QTILES + qt) * MAXSPLIT;
    float* Ob = out + (size_t)(b * TLEN + qt * 64) * HDIM;

    #pragma unroll
    for (int r = 0; r < 4; r++) {
        const int row = ty * 4 + r;

        float ms[MAXSPLIT], ls[MAXSPLIT], sc[MAXSPLIT];
        float mstar = -1e30f;
        for (int s = 0; s < S; s++) {
            ms[s] = g_pm[(base + s) * 64 + row];
            ls[s] = g_pl[(base + s) * 64 + row];
            mstar = fmaxf(mstar, ms[s]);
        }
        float lstar = 0.0f;
        for (int s = 0; s < S; s++) {
            sc[s] = __expf(ms[s] - mstar);
            lstar += ls[s] * sc[s];
        }
        const float inv = 1.0f / lstar;

        float4 o = make_float4(0.f, 0.f, 0.f, 0.f);
        for (int s = 0; s < S; s++) {
            const float4 p = *(const float4*)&g_Op[(base + s) * 4096 + row * 64 + tx * 4];
            o.x += p.x * sc[s];
            o.y += p.y * sc[s];
            o.z += p.z * sc[s];
            o.w += p.w * sc[s];
        }
        o.x *= inv; o.y *= inv; o.z *= inv; o.w *= inv;
        *(float4*)&Ob[row * HDIM + tx * 4] = o;
    }
}

// ----------------------------------------------------------------------------
// Harness entry
// ----------------------------------------------------------------------------
extern "C" void kernel_launch(void* const* d_in, const int* in_sizes, int n_in,
                              void* d_out, int out_size)
{
    const float* x  = (const float*)d_in[0];
    const float* Wq = (const float*)d_in[1];
    const float* Wk = (const float*)d_in[2];
    const float* Wv = (const float*)d_in[3];
    float* out = (float*)d_out;

    (void)in_sizes; (void)n_in; (void)out_size;

    qkv_proj<<<QKV_BLOCKS, QKV_THREADS>>>(x, Wq, Wk, Wv);

    cudaFuncSetAttribute(attn_kernel, cudaFuncAttributeMaxDynamicSharedMemorySize,
                         (int)ATTN_SMEM);
    attn_kernel<<<dim3(BLOCKS_PER_BATCH, BATCH), 256, ATTN_SMEM>>>();

    attn_combine<<<dim3(QTILES, BATCH), 256>>>(out);
}

// round 15
// speedup vs baseline: 2.0425x; 1.0021x over previous
#include <cuda_runtime.h>
#include <math.h>
#include <stdint.h>

// Problem constants
#define BATCH   8
#define TLEN    2048
#define CDIM    1024
#define HDIM    64
#define BT      (BATCH * TLEN)   // 16384 rows

#define QTILES   32
#define CHUNK    8
#define MAXSPLIT 4
#define BLOCKS_PER_BATCH 80      // sum over qt of (qt/CHUNK + 1)

// qkv grid: 56-row slabs, 293 blocks -> single wave on 148 SMs x 2 resident
#define QKV_ROWS   56
#define QKV_BLOCKS 293           // ceil(16384 / 56)
#define QKV_THREADS 224          // 14 ty-groups x 16 tx

// Scratch (__device__ globals per harness rules)
__device__ float g_Q[BT * HDIM];
__device__ float g_K[BT * HDIM];
__device__ float g_V[BT * HDIM];
__device__ float g_Op[BATCH * QTILES * MAXSPLIT * 64 * 64];
__device__ float g_pm[BATCH * QTILES * MAXSPLIT * 64];
__device__ float g_pl[BATCH * QTILES * MAXSPLIT * 64];

// ---------------------------------------------------------------------------
// cp.async helpers
// ---------------------------------------------------------------------------
__device__ __forceinline__ void cp16(uint32_t smem_dst, const void* gsrc) {
    asm volatile("cp.async.ca.shared.global [%0], [%1], 16;"
                 :: "r"(smem_dst), "l"(gsrc));
}
__device__ __forceinline__ void cp_commit() { asm volatile("cp.async.commit_group;"); }
__device__ __forceinline__ void cp_wait0() { asm volatile("cp.async.wait_group 0;"); }
__device__ __forceinline__ void cp_wait1() { asm volatile("cp.async.wait_group 1;"); }

// ---------------------------------------------------------------------------
// f32x2 packed helpers (exact fp32)
// ---------------------------------------------------------------------------
__device__ __forceinline__ unsigned long long dup2(float a) {
    unsigned long long r;
    asm("mov.b64 %0, {%1, %1};" : "=l"(r) : "f"(a));
    return r;
}
__device__ __forceinline__ void ffma2(unsigned long long& acc,
                                      unsigned long long a,
                                      unsigned long long b) {
    asm("fma.rn.f32x2 %0, %1, %2, %0;" : "+l"(acc) : "l"(a), "l"(b));
}
__device__ __forceinline__ void fmul2(unsigned long long& v,
                                      unsigned long long s) {
    asm("mul.rn.f32x2 %0, %0, %1;" : "+l"(v) : "l"(s));
}
__device__ __forceinline__ float2 unpack2(unsigned long long v) {
    float lo, hi;
    asm("mov.b64 {%0, %1}, %2;" : "=f"(lo), "=f"(hi) : "l"(v));
    return make_float2(lo, hi);
}
__device__ __forceinline__ float hsum2(unsigned long long v) {
    float2 f = unpack2(v);
    return f.x + f.y;
}

// ----------------------------------------------------------------------------
// Kernel 1: fused QKV projection (exact R9/R14 config: measured 148us).
// ----------------------------------------------------------------------------
__global__ __launch_bounds__(QKV_THREADS) void qkv_proj(
    const float* __restrict__ x,
    const float* __restrict__ Wq,
    const float* __restrict__ Wk,
    const float* __restrict__ Wv)
{
    __shared__ float xs[16][QKV_ROWS];      // [kk][row]
    __shared__ float ws[2][3][16][64];      // double-buffered W tiles

    const int tid = threadIdx.x;
    const int tx  = tid & 15;               // 0..15 (col group)
    const int ty  = tid >> 4;               // 0..13 (row group)
    const int rowBase = min(blockIdx.x * QKV_ROWS, BT - QKV_ROWS);

    const uint32_t ws_base = (uint32_t)__cvta_generic_to_shared(&ws[0][0][0][0]);
    const uint32_t ws_buf_bytes = 3 * 16 * 64 * 4;

    const int xr  = tid >> 2;               // 0..55
    const int xk4 = (tid & 3) * 4;          // 0,4,8,12

    const float* Wmat[3] = {Wq, Wk, Wv};

    float4 xreg = *(const float4*)&x[(size_t)(rowBase + xr) * CDIM + 0 + xk4];
    {
        #pragma unroll
        for (int m = 0; m < 3; m++)
            for (int i = tid; i < 256; i += QKV_THREADS) {
                const int kk = i >> 4, c4 = (i & 15) * 4;
                cp16(ws_base + (uint32_t)m * (16 * 64 * 4)
                             + (uint32_t)((kk * 64 + c4) * 4),
                     &Wmat[m][(size_t)(0 + kk) * HDIM + c4]);
            }
        cp_commit();
    }

    unsigned long long acc2[3][4][2];
    #pragma unroll
    for (int m = 0; m < 3; m++)
        #pragma unroll
        for (int r = 0; r < 4; r++) {
            acc2[m][r][0] = 0ULL;
            acc2[m][r][1] = 0ULL;
        }

    int buf = 0;
    for (int k0 = 0; k0 < CDIM; k0 += 16, buf ^= 1) {
        xs[xk4 + 0][xr] = xreg.x;
        xs[xk4 + 1][xr] = xreg.y;
        xs[xk4 + 2][xr] = xreg.z;
        xs[xk4 + 3][xr] = xreg.w;

        const bool has_next = (k0 + 16) < CDIM;
        if (has_next) {
            const uint32_t dbase = ws_base + (uint32_t)(buf ^ 1) * ws_buf_bytes;
            #pragma unroll
            for (int m = 0; m < 3; m++)
                for (int i = tid; i < 256; i += QKV_THREADS) {
                    const int kk = i >> 4, c4 = (i & 15) * 4;
                    cp16(dbase + (uint32_t)m * (16 * 64 * 4)
                               + (uint32_t)((kk * 64 + c4) * 4),
                         &Wmat[m][(size_t)(k0 + 16 + kk) * HDIM + c4]);
                }
            cp_commit();
            cp_wait1();
        } else {
            cp_wait0();
        }
        __syncthreads();

        if (has_next)
            xreg = *(const float4*)&x[(size_t)(rowBase + xr) * CDIM + k0 + 16 + xk4];

        #pragma unroll
        for (int kk = 0; kk < 16; kk++) {
            const float4 a4 = *(const float4*)&xs[kk][ty * 4];
            unsigned long long ad[4];
            ad[0] = dup2(a4.x); ad[1] = dup2(a4.y);
            ad[2] = dup2(a4.z); ad[3] = dup2(a4.w);
            #pragma unroll
            for (int m = 0; m < 3; m++) {
                const ulonglong2 b2 = *(const ulonglong2*)&ws[buf][m][kk][tx * 4];
                #pragma unroll
                for (int r = 0; r < 4; r++) {
                    ffma2(acc2[m][r][0], ad[r], b2.x);
                    ffma2(acc2[m][r][1], ad[r], b2.y);
                }
            }
        }
        __syncthreads();
    }

    #pragma unroll
    for (int r = 0; r < 4; r++) {
        const int row = rowBase + ty * 4 + r;
        const int col = tx * 4;
        float2 qlo = unpack2(acc2[0][r][0]), qhi = unpack2(acc2[0][r][1]);
        float2 klo = unpack2(acc2[1][r][0]), khi = unpack2(acc2[1][r][1]);
        float2 vlo = unpack2(acc2[2][r][0]), vhi = unpack2(acc2[2][r][1]);
        *(float4*)&g_Q[(size_t)row * HDIM + col] = make_float4(qlo.x, qlo.y, qhi.x, qhi.y);
        *(float4*)&g_K[(size_t)row * HDIM + col] = make_float4(klo.x, klo.y, khi.x, khi.y);
        *(float4*)&g_V[(size_t)row * HDIM + col] = make_float4(vlo.x, vlo.y, vhi.x, vhi.y);
    }
}

// ----------------------------------------------------------------------------
// Kernel 2: causal flash attention, split-K, LPT, strided score columns
// (R14 bank fix) + f32x2 packed math (now unmasked by the conflict fix).
// QK^T packs over reduction dim d; PV packs over output-dim pairs.
// ----------------------------------------------------------------------------
#define PAD 68
#define ATTN_SMEM (6 * 64 * PAD * sizeof(float))   // 104448 bytes

__global__ __launch_bounds__(256) void attn_kernel()
{
    extern __shared__ float smem[];
    float* qs  = smem;
    float* ksb[2] = { qs + 1 * 64 * PAD, qs + 2 * 64 * PAD };
    float* vsb[2] = { qs + 3 * 64 * PAD, qs + 4 * 64 * PAD };
    float* ps  = qs + 5 * 64 * PAD;

    const uint32_t sbase = (uint32_t)__cvta_generic_to_shared(smem);

    // LPT: reverse linear id so qt=31 (8-iter) blocks start first
    int lin = (BLOCKS_PER_BATCH - 1) - blockIdx.x;
    int qt = 0;
    while (true) {
        const int S = qt / CHUNK + 1;
        if (lin < S) break;
        lin -= S;
        qt++;
    }
    const int sp  = lin;
    const int kt0 = sp * CHUNK;
    const int kt1 = min(kt0 + CHUNK, qt + 1);

    const int b   = blockIdx.y;
    const int tid = threadIdx.x;
    const int tx  = tid & 15;
    const int ty  = tid >> 4;
    const float scale = 0.125f;

    const float* Kbase = g_K + (size_t)b * TLEN * HDIM;
    const float* Vbase = g_V + (size_t)b * TLEN * HDIM;

    {
        const float* Kb = Kbase + (size_t)kt0 * 64 * HDIM;
        const float* Vb = Vbase + (size_t)kt0 * 64 * HDIM;
        const uint32_t ks_off = sbase + (uint32_t)(1 * 64 * PAD) * 4;
        const uint32_t vs_off = sbase + (uint32_t)(3 * 64 * PAD) * 4;
        #pragma unroll
        for (int i = tid; i < 1024; i += 256) {
            const int r  = i >> 4;
            const int c4 = (i & 15) * 4;
            const uint32_t d = (uint32_t)((r * PAD + c4) * 4);
            cp16(ks_off + d, &Kb[r * HDIM + c4]);
            cp16(vs_off + d, &Vb[r * HDIM + c4]);
        }
        cp_commit();
    }

    {
        const float* Qb = g_Q + (size_t)(b * TLEN + qt * 64) * HDIM;
        #pragma unroll
        for (int i = tid; i < 1024; i += 256) {
            const int r  = i >> 4;
            const int c4 = (i & 15) * 4;
            float4 v = *(const float4*)&Qb[r * HDIM + c4];
            v.x *= scale; v.y *= scale; v.z *= scale; v.w *= scale;
            *(float4*)&qs[r * PAD + c4] = v;
        }
    }

    float m_i[4], l_i[4];
    unsigned long long acc2[4][2];   // [row][output-dim pair], cols tx*4..tx*4+3
    #pragma unroll
    for (int r = 0; r < 4; r++) {
        m_i[r] = -1e30f;
        l_i[r] = 0.0f;
        acc2[r][0] = 0ULL;
        acc2[r][1] = 0ULL;
    }

    int buf = 0;
    for (int kt = kt0; kt < kt1; kt++, buf ^= 1) {
        const bool has_next = (kt + 1) < kt1;
        if (has_next) {
            const float* Kb = Kbase + (size_t)(kt + 1) * 64 * HDIM;
            const float* Vb = Vbase + (size_t)(kt + 1) * 64 * HDIM;
            const uint32_t ks_off = sbase + (uint32_t)((1 + (buf ^ 1)) * 64 * PAD) * 4;
            const uint32_t vs_off = sbase + (uint32_t)((3 + (buf ^ 1)) * 64 * PAD) * 4;
            #pragma unroll
            for (int i = tid; i < 1024; i += 256) {
                const int r  = i >> 4;
                const int c4 = (i & 15) * 4;
                const uint32_t d = (uint32_t)((r * PAD + c4) * 4);
                cp16(ks_off + d, &Kb[r * HDIM + c4]);
                cp16(vs_off + d, &Vb[r * HDIM + c4]);
            }
            cp_commit();
            cp_wait1();
        } else {
            cp_wait0();
        }
        __syncthreads();

        const float* ks = ksb[buf];
        const float* vs = vsb[buf];

        // Scores: strided columns tx+16c (conflict-free), packed over d
        unsigned long long s2[4][4];
        #pragma unroll
        for (int r = 0; r < 4; r++)
            #pragma unroll
            for (int c = 0; c < 4; c++) s2[r][c] = 0ULL;

        #pragma unroll
        for (int d = 0; d < HDIM; d += 4) {
            ulonglong2 q2[4], k2[4];
            #pragma unroll
            for (int r = 0; r < 4; r++)
                q2[r] = *(const ulonglong2*)&qs[(ty * 4 + r) * PAD + d];
            #pragma unroll
            for (int c = 0; c < 4; c++)
                k2[c] = *(const ulonglong2*)&ks[(tx + 16 * c) * PAD + d];
            #pragma unroll
            for (int r = 0; r < 4; r++)
                #pragma unroll
                for (int c = 0; c < 4; c++) {
                    ffma2(s2[r][c], q2[r].x, k2[c].x);
                    ffma2(s2[r][c], q2[r].y, k2[c].y);
                }
        }

        float s[4][4];
        #pragma unroll
        for (int r = 0; r < 4; r++)
            #pragma unroll
            for (int c = 0; c < 4; c++) s[r][c] = hsum2(s2[r][c]);

        // Causal mask on the diagonal tile (strided column index)
        if (kt == qt) {
            #pragma unroll
            for (int r = 0; r < 4; r++)
                #pragma unroll
                for (int c = 0; c < 4; c++)
                    if (tx + 16 * c > ty * 4 + r) s[r][c] = -1e30f;
        }

        // Online softmax update (row reductions across the 16 tx lanes)
        #pragma unroll
        for (int r = 0; r < 4; r++) {
            float mx = fmaxf(fmaxf(s[r][0], s[r][1]), fmaxf(s[r][2], s[r][3]));
            #pragma unroll
            for (int o = 8; o >= 1; o >>= 1)
                mx = fmaxf(mx, __shfl_xor_sync(0xffffffffu, mx, o));
            const float mnew = fmaxf(m_i[r], mx);

            float sum = 0.0f;
            #pragma unroll
            for (int c = 0; c < 4; c++) {
                s[r][c] = __expf(s[r][c] - mnew);
                sum += s[r][c];
            }
            #pragma unroll
            for (int o = 8; o >= 1; o >>= 1)
                sum += __shfl_xor_sync(0xffffffffu, sum, o);

            const float corr = __expf(m_i[r] - mnew);
            l_i[r] = l_i[r] * corr + sum;
            const unsigned long long corr2 = dup2(corr);
            fmul2(acc2[r][0], corr2);
            fmul2(acc2[r][1], corr2);
            m_i[r] = mnew;
        }

        // Stage P to shared at strided columns (conflict-free scalar stores)
        #pragma unroll
        for (int r = 0; r < 4; r++)
            #pragma unroll
            for (int c = 0; c < 4; c++)
                ps[(ty * 4 + r) * PAD + tx + 16 * c] = s[r][c];
        __syncthreads();

        // O += P . V : packed over output-dim pairs (V pairs contiguous at
        // tx*4, 2-phase; P broadcast via dup2 on ALU pipe)
        #pragma unroll
        for (int j = 0; j < 64; j += 4) {
            float4 p4[4];
            ulonglong2 v2[4];
            #pragma unroll
            for (int r = 0; r < 4; r++)
                p4[r] = *(const float4*)&ps[(ty * 4 + r) * PAD + j];
            #pragma unroll
            for (int jj = 0; jj < 4; jj++)
                v2[jj] = *(const ulonglong2*)&vs[(j + jj) * PAD + tx * 4];
            #pragma unroll
            for (int r = 0; r < 4; r++) {
                const unsigned long long pd0 = dup2(p4[r].x);
                const unsigned long long pd1 = dup2(p4[r].y);
                const unsigned long long pd2 = dup2(p4[r].z);
                const unsigned long long pd3 = dup2(p4[r].w);
                ffma2(acc2[r][0], pd0, v2[0].x);
                ffma2(acc2[r][1], pd0, v2[0].y);
                ffma2(acc2[r][0], pd1, v2[1].x);
                ffma2(acc2[r][1], pd1, v2[1].y);
                ffma2(acc2[r][0], pd2, v2[2].x);
                ffma2(acc2[r][1], pd2, v2[2].y);
                ffma2(acc2[r][0], pd3, v2[3].x);
                ffma2(acc2[r][1], pd3, v2[3].y);
            }
        }
        __syncthreads();
    }

    // Write unnormalized partials + (m, l)
    const size_t pbase = (size_t)((b * QTILES + qt) * MAXSPLIT + sp);
    float* Ob = g_Op + pbase * 4096;
    #pragma unroll
    for (int r = 0; r < 4; r++) {
        const float2 lo = unpack2(acc2[r][0]);
        const float2 hi = unpack2(acc2[r][1]);
        *(float4*)&Ob[(ty * 4 + r) * 64 + tx * 4] =
            make_float4(lo.x, lo.y, hi.x, hi.y);
    }
    if (tx == 0) {
        #pragma unroll
        for (int r = 0; r < 4; r++) {
            g_pm[pbase * 64 + ty * 4 + r] = m_i[r];
            g_pl[pbase * 64 + ty * 4 + r] = l_i[r];
        }
    }
}

// ----------------------------------------------------------------------------
// Kernel 3: combine split-K partials (unchanged).
// ----------------------------------------------------------------------------
__global__ __launch_bounds__(256) void attn_combine(float* __restrict__ out)
{
    const int qt  = blockIdx.x;
    const int b   = blockIdx.y;
    const int S   = qt / CHUNK + 1;
    const int tid = threadIdx.x;
    const int tx  = tid & 15;
    const int ty  = tid >> 4;

    const size_t base = (size_t)(b * QTILES + qt) * MAXSPLIT;
    float* Ob = out + (size_t)(b * TLEN + qt * 64) * HDIM;

    #pragma unroll
    for (int r = 0; r < 4; r++) {
        const int row = ty * 4 + r;

        float ms[MAXSPLIT], ls[MAXSPLIT], sc[MAXSPLIT];
        float mstar = -1e30f;
        for (int s = 0; s < S; s++) {
            ms[s] = g_pm[(base + s) * 64 + row];
            ls[s] = g_pl[(base + s) * 64 + row];
            mstar = fmaxf(mstar, ms[s]);
        }
        float lstar = 0.0f;
        for (int s = 0; s < S; s++) {
            sc[s] = __expf(ms[s] - mstar);
            lstar += ls[s] * sc[s];
        }
        const float inv = 1.0f / lstar;

        float4 o = make_float4(0.f, 0.f, 0.f, 0.f);
        for (int s = 0; s < S; s++) {
            const float4 p = *(const float4*)&g_Op[(base + s) * 4096 + row * 64 + tx * 4];
            o.x += p.x * sc[s];
            o.y += p.y * sc[s];
            o.z += p.z * sc[s];
            o.w += p.w * sc[s];
        }
        o.x *= inv; o.y *= inv; o.z *= inv; o.w *= inv;
        *(float4*)&Ob[row * HDIM + tx * 4] = o;
    }
}

// ----------------------------------------------------------------------------
// Harness entry
// ----------------------------------------------------------------------------
extern "C" void kernel_launch(void* const* d_in, const int* in_sizes, int n_in,
                              void* d_out, int out_size)
{
    const float* x  = (const float*)d_in[0];
    const float* Wq = (const float*)d_in[1];
    const float* Wk = (const float*)d_in[2];
    const float* Wv = (const float*)d_in[3];
    float* out = (float*)d_out;

    (void)in_sizes; (void)n_in; (void)out_size;

    qkv_proj<<<QKV_BLOCKS, QKV_THREADS>>>(x, Wq, Wk, Wv);

    cudaFuncSetAttribute(attn_kernel, cudaFuncAttributeMaxDynamicSharedMemorySize,
                         (int)ATTN_SMEM);
    attn_kernel<<<dim3(BLOCKS_PER_BATCH, BATCH), 256, ATTN_SMEM>>>();

    attn_combine<<<dim3(QTILES, BATCH), 256>>>(out);
}